// round 11
// baseline (speedup 1.0000x reference)
#include <cuda_runtime.h>

// Problem shape (fixed by the reference):
//   z: (16, 3, 256, 256) f32 ; out: (16, 3, 256, 256) f32
#define HID   64
#define ZCH   3
#define TD    512
#define NB    16
#define HWP   (256 * 256)          // pixels per (b, ch) plane
#define HW4   (HWP / 4)            // float4 groups per plane = 16384

#define LOG2E 1.4426950408889634f

// ---------------------------------------------------------------------------
// Constants, packed as float4. PRE-SCALED so the main body uses bare
// ex2.approx for both exponentials:
//   dist' = -gamma*log2e * (z'Mz + d.z + e)  built from scaled M',d',e'
//   k2    = W0*E1 + B1*klin + B2*klin^2 + B0   (= -log2e * k)
// Layout:
//   g_cv[0] = (M00', M11', M22', M01'2)   (diag: -gl2*m ; offdiag: -2*gl2*m)
//   g_cv[1] = (M02'2, M12'2, W0, B1)
//   g_cv[2] = (B2, B0, -, -)
//   g_cv[3] = (P00, P01, P02, r0)
//   g_cv[4] = (P10, P11, P12, r1)
//   g_cv[5] = (P20, P21, P22, r2)
//   g_cv[6] = (ob0, ob1, ob2, 0)
//   g_pb[b][0] = (d0', d1', d2', e')      (scaled by -gl2; d = 2 A^T u)
//   g_pb[b][1] = (q0, q1, q2, s)          (unscaled; klin = q.z + s)
// ---------------------------------------------------------------------------
__device__ float4 g_cv[7];
__device__ float4 g_pb[NB][2];

__device__ __forceinline__ float wsum(float v) {
    #pragma unroll
    for (int o = 16; o; o >>= 1) v += __shfl_xor_sync(0xffffffffu, v, o);
    return v;
}

__device__ __forceinline__ float ex2(float x) {
    float r;
    asm("ex2.approx.f32 %0, %1;" : "=f"(r) : "f"(x));
    return r;
}

// ---------------------------------------------------------------------------
// Prep: one block per batch, 256 threads (8 warps). Warp w owns GEMV outputs
// o = 8w..8w+7, fully unrolled (32 independent LDG.128 per lane).
// ---------------------------------------------------------------------------
__global__ void __launch_bounds__(256) prep_kernel(
    const float* __restrict__ tv,   // (NB, TD)
    const float* __restrict__ A,    // (HID, 3) z_proj_w
    const float* __restrict__ zpb,  // (HID,)   z_proj_b
    const float* __restrict__ tw,   // (HID, TD)
    const float* __restrict__ tpb,  // (HID,)
    const float* __restrict__ W,    // (3, HID) out_w
    const float* __restrict__ ob,   // (3,)
    const float* __restrict__ lg,   // log_gamma
    const float* __restrict__ al,   // alpha
    const float* __restrict__ cp,   // c
    const float* __restrict__ wv)   // (3,)
{
    __shared__ float4 tv_sh[TD / 4];
    __shared__ float t_sh[HID], u_sh[HID], zpb_sh[HID];
    __shared__ float A_sh[HID * 3], W_sh[3 * HID];

    const int b    = blockIdx.x;
    const int tid  = threadIdx.x;
    const int wid  = tid >> 5;
    const int lane = tid & 31;

    if (tid < TD / 4)   tv_sh[tid]  = ((const float4*)(tv + b * TD))[tid];
    if (tid < HID * 3)  A_sh[tid]   = A[tid];
    if (tid < 3 * HID)  W_sh[tid]   = W[tid];
    if (tid < HID)      zpb_sh[tid] = zpb[tid];
    __syncthreads();

    // GEMV: warp w owns 8 outputs; 8 independent accumulators.
    {
        const float4* tw4 = (const float4*)tw;
        float acc[8];
        #pragma unroll
        for (int j = 0; j < 8; j++) acc[j] = 0.f;
        #pragma unroll
        for (int k = 0; k < 4; k++) {
            const float4 v = tv_sh[k * 32 + lane];
            #pragma unroll
            for (int j = 0; j < 8; j++) {
                const int o = wid * 8 + j;
                const float4 a = tw4[o * (TD / 4) + k * 32 + lane];
                acc[j] = fmaf(a.x, v.x, fmaf(a.y, v.y, fmaf(a.z, v.z, fmaf(a.w, v.w, acc[j]))));
            }
        }
        #pragma unroll
        for (int j = 0; j < 8; j++) {
            const float s = wsum(acc[j]);
            const int o = wid * 8 + j;
            if (lane == 0) {
                const float tval = s + tpb[o];
                t_sh[o] = tval;
                u_sh[o] = zpb_sh[o] - tval;   // u = zb - t
            }
        }
    }
    __syncthreads();

    float* cf  = (float*)g_cv;
    float* pbf = (float*)g_pb;

    const float tl = t_sh[lane],   th = t_sh[lane + 32];
    const float ul = u_sh[lane],   uh = u_sh[lane + 32];
    const float zl = zpb_sh[lane], zh = zpb_sh[lane + 32];

    // -gamma*log2e, available cheaply in any warp that needs it
    const float ngl2 = -expf(lg[0]) * LOG2E;

    if (wid == 0) {
        // per-batch d' = ngl2 * 2 A^T u, q = A^T t
        #pragma unroll
        for (int i = 0; i < 3; i++) {
            const float a1 = A_sh[lane * 3 + i], a2 = A_sh[(lane + 32) * 3 + i];
            float d = wsum(a1 * ul + a2 * uh);
            float q = wsum(a1 * tl + a2 * th);
            if (lane == 0) { pbf[b * 8 + i] = ngl2 * 2.f * d; pbf[b * 8 + 4 + i] = q; }
        }
    } else if (wid == 1) {
        // per-batch e' = ngl2 * |u|^2, s = t . zb
        float e  = wsum(ul * ul + uh * uh);
        float s2 = wsum(tl * zl + th * zh);
        if (lane == 0) { pbf[b * 8 + 3] = ngl2 * e; pbf[b * 8 + 7] = s2; }
    }

    if (b == 0) {
        if (wid == 2) {
            // M' = ngl2 * (A^T A)  (diag), 2*ngl2*m (offdiag)
            const int ii[6] = {0, 1, 2, 0, 0, 1};
            const int jj[6] = {0, 1, 2, 1, 2, 2};
            #pragma unroll
            for (int k = 0; k < 6; k++) {
                float m = wsum(A_sh[lane * 3 + ii[k]] * A_sh[lane * 3 + jj[k]]
                             + A_sh[(lane + 32) * 3 + ii[k]] * A_sh[(lane + 32) * 3 + jj[k]]);
                if (lane == 0) cf[k] = (k < 3) ? ngl2 * m : 2.f * ngl2 * m;
            }
        } else if (wid == 3) {
            // P = W A  -> cf[12 + 4*i + j]
            #pragma unroll
            for (int i = 0; i < 3; i++)
                #pragma unroll
                for (int j = 0; j < 3; j++) {
                    float p = wsum(W_sh[i * HID + lane] * A_sh[lane * 3 + j]
                                 + W_sh[i * HID + lane + 32] * A_sh[(lane + 32) * 3 + j]);
                    if (lane == 0) cf[12 + 4 * i + j] = p;
                }
        } else if (wid == 4) {
            // r = W zb ; polynomial-expanded k coefficients (scaled by -log2e)
            #pragma unroll
            for (int i = 0; i < 3; i++) {
                float rr = wsum(W_sh[i * HID + lane] * zl + W_sh[i * HID + lane + 32] * zh);
                if (lane == 0) cf[15 + 4 * i] = rr;
            }
            if (lane == 0) {
                const float w0 = wv[0], w1 = wv[1], w2 = wv[2];
                const float inv = 1.f / (w0 + w1 + w2 + 1e-8f);
                const float w0n = w0 * inv, w1n = w1 * inv, w2n = w2 * inv;
                const float alpha = al[0], ccc = cp[0];
                // k = w0n*E1 + (w1n + 2 w2n a c)*klin + (w2n a^2)*klin^2 + w2n c^2
                cf[6] = -LOG2E * w0n;                                // W0
                cf[7] = -LOG2E * (w1n + 2.f * w2n * alpha * ccc);    // B1
                cf[8] = -LOG2E * (w2n * alpha * alpha);              // B2
                cf[9] = -LOG2E * (w2n * ccc * ccc);                  // B0
            }
            if (lane >= 1 && lane <= 3) cf[24 + lane - 1] = ob[lane - 1];
        }
    }
}

// ---------------------------------------------------------------------------
// Main: R10's measured-best shape (1024 x 256, one float4-triple/thread),
// minimal body: 2 bare ex2.approx, poly-expanded k, fast-divide sigmoid.
// ---------------------------------------------------------------------------
__global__ void __launch_bounds__(256) fused_main_kernel(
    const float* __restrict__ z, float* __restrict__ out)
{
    const unsigned g  = blockIdx.x * 256u + threadIdx.x;
    const int b  = (int)(g >> 14);        // / HW4
    const int p4 = (int)(g & (HW4 - 1));

    const float4* zb4 = (const float4*)(z   + (size_t)b * ZCH * HWP);
    float4*       ob4 = (float4*)      (out + (size_t)b * ZCH * HWP);

    // front-batched data loads (MLP=3)
    const float4 v0 = zb4[p4];
    const float4 v1 = zb4[p4 + HW4];
    const float4 v2 = zb4[p4 + 2 * HW4];

    // vectorized constant loads (9 x LDG.128, broadcast)
    const float4 c0 = g_cv[0], c1 = g_cv[1], c2 = g_cv[2];
    const float4 c3 = g_cv[3], c4 = g_cv[4], c5 = g_cv[5], c6 = g_cv[6];
    const float4 p0 = g_pb[b][0], p1 = g_pb[b][1];

    const float M00 = c0.x, M11 = c0.y, M22 = c0.z, M01 = c0.w;
    const float M02 = c1.x, M12 = c1.y, W0 = c1.z, B1 = c1.w;
    const float B2 = c2.x, B0 = c2.y;
    const float d0 = p0.x, d1 = p0.y, d2 = p0.z, e = p0.w;
    const float q0 = p1.x, q1 = p1.y, q2 = p1.z, s = p1.w;

    const float a0[4] = { v0.x, v0.y, v0.z, v0.w };
    const float a1[4] = { v1.x, v1.y, v1.z, v1.w };
    const float a2[4] = { v2.x, v2.y, v2.z, v2.w };
    float o0[4], o1[4], o2[4];

    #pragma unroll
    for (int i = 0; i < 4; i++) {
        const float x = a0[i], y = a1[i], zz = a2[i];

        // dist' = -gamma*log2e * (z'Mz + d.z + e)  (all pre-scaled)
        float dist = e;
        dist = fmaf(fmaf(M00, x, fmaf(M01, y, fmaf(M02, zz, d0))), x, dist);
        dist = fmaf(fmaf(M11, y, fmaf(M12, zz, d1)),               y, dist);
        dist = fmaf(fmaf(M22, zz, d2),                             zz, dist);
        const float E1 = ex2(dist);                 // = exp(-gamma*dist)

        // klin = q.z + s
        const float klin = fmaf(q0, x, fmaf(q1, y, fmaf(q2, zz, s)));

        // k2 = -log2e * k  (poly-expanded)
        const float k2 = fmaf(W0, E1, fmaf(klin, fmaf(B2, klin, B1), B0));
        const float E2 = ex2(k2);                   // = exp(-k)

        // scale = 1 + sigmoid(k) = (2 + E2) / (1 + E2)
        const float scale = __fdividef(2.f + E2, 1.f + E2);

        o0[i] = fmaf(scale, fmaf(c3.x, x, fmaf(c3.y, y, fmaf(c3.z, zz, c3.w))), c6.x);
        o1[i] = fmaf(scale, fmaf(c4.x, x, fmaf(c4.y, y, fmaf(c4.z, zz, c4.w))), c6.y);
        o2[i] = fmaf(scale, fmaf(c5.x, x, fmaf(c5.y, y, fmaf(c5.z, zz, c5.w))), c6.z);
    }

    ob4[p4]           = make_float4(o0[0], o0[1], o0[2], o0[3]);
    ob4[p4 + HW4]     = make_float4(o1[0], o1[1], o1[2], o1[3]);
    ob4[p4 + 2 * HW4] = make_float4(o2[0], o2[1], o2[2], o2[3]);
}

// ---------------------------------------------------------------------------
extern "C" void kernel_launch(void* const* d_in, const int* in_sizes, int n_in,
                              void* d_out, int out_size)
{
    const float* z    = (const float*)d_in[0];
    const float* tv   = (const float*)d_in[1];
    const float* zpw  = (const float*)d_in[2];
    const float* zpb  = (const float*)d_in[3];
    const float* tw   = (const float*)d_in[4];
    const float* tpb  = (const float*)d_in[5];
    const float* ow   = (const float*)d_in[6];
    const float* ob   = (const float*)d_in[7];
    const float* lg   = (const float*)d_in[8];
    const float* al   = (const float*)d_in[9];
    const float* cp   = (const float*)d_in[10];
    const float* wv   = (const float*)d_in[11];
    float* out = (float*)d_out;

    const int B = in_sizes[0] / (ZCH * HWP);      // 16

    prep_kernel<<<NB, 256>>>(tv, zpw, zpb, tw, tpb, ow, ob, lg, al, cp, wv);
    fused_main_kernel<<<(B * HW4) / 256, 256>>>(z, out);
}

// round 12
// speedup vs baseline: 1.2209x; 1.2209x over previous
#include <cuda_runtime.h>

// Problem shape (fixed by the reference):
//   z: (16, 3, 256, 256) f32 ; out: (16, 3, 256, 256) f32
#define HID   64
#define ZCH   3
#define TD    512
#define NB    16
#define HWP   (256 * 256)          // pixels per (b, ch) plane
#define HW4   (HWP / 4)            // float4 groups per plane = 16384

// ---------------------------------------------------------------------------
// Global constants (R10 layout):
//   g_cv[0] = (M00, M11, M22, 2*M01)
//   g_cv[1] = (2*M02, 2*M12, gamma, alpha)
//   g_cv[2] = (c, w0n, w1n, w2n)
//   g_cv[3] = (P00, P01, P02, r0)
//   g_cv[4] = (P10, P11, P12, r1)
//   g_cv[5] = (P20, P21, P22, r2)
//   g_cv[6] = (ob0, ob1, ob2, 0)
// Per-batch PARTIALS (4 quarter-blocks per batch, summed by main):
//   g_part[b][qt][0] = partial (d0, d1, d2, e)   over outputs o in quarter qt
//   g_part[b][qt][1] = partial (q0, q1, q2, s)
// where d = 2 A^T u, e = |u|^2, q = A^T t, s = t.zb,  u = zb - t(b).
// ---------------------------------------------------------------------------
__device__ float4 g_cv[7];
__device__ float4 g_part[NB][4][2];

__device__ __forceinline__ float wsum(float v) {
    #pragma unroll
    for (int o = 16; o; o >>= 1) v += __shfl_xor_sync(0xffffffffu, v, o);
    return v;
}

// ---------------------------------------------------------------------------
// Prep, 65 blocks x 256 threads:
//   blocks 0..63 : batch b = bid>>2, quarter qt = bid&3 -> 16 GEMV outputs,
//                  2 per warp; then warp 0 reduces the 16 per-output
//                  contributions into the two partial float4s.
//   block 64     : global constants, reduction chains spread across warps
//                  (<=3 chains per warp instead of 9 serial on one warp).
// ---------------------------------------------------------------------------
__global__ void __launch_bounds__(256) prep_kernel(
    const float* __restrict__ tv,   // (NB, TD)
    const float* __restrict__ A,    // (HID, 3) z_proj_w
    const float* __restrict__ zpb,  // (HID,)   z_proj_b
    const float* __restrict__ tw,   // (HID, TD)
    const float* __restrict__ tpb,  // (HID,)
    const float* __restrict__ W,    // (3, HID) out_w
    const float* __restrict__ ob,   // (3,)
    const float* __restrict__ lg,   // log_gamma
    const float* __restrict__ al,   // alpha
    const float* __restrict__ cp,   // c
    const float* __restrict__ wv)   // (3,)
{
    const int bid  = (int)blockIdx.x;
    const int tid  = (int)threadIdx.x;
    const int wid  = tid >> 5;
    const int lane = tid & 31;

    if (bid < 64) {
        // ---------------- per-batch quarter block ----------------
        __shared__ float4 tv_sh[TD / 4];
        __shared__ float t_loc[16], u_loc[16];

        const int b      = bid >> 2;
        const int qt     = bid & 3;
        const int base_o = qt * 16;

        if (tid < TD / 4) tv_sh[tid] = ((const float4*)(tv + b * TD))[tid];
        __syncthreads();

        // GEMV: warp w owns outputs base_o + 2w, base_o + 2w + 1
        const float4* tw4 = (const float4*)tw;
        float acc[2] = {0.f, 0.f};
        #pragma unroll
        for (int j = 0; j < 2; j++) {
            const int o = base_o + wid * 2 + j;
            #pragma unroll
            for (int k = 0; k < 4; k++) {
                const float4 a = tw4[o * (TD / 4) + k * 32 + lane];
                const float4 v = tv_sh[k * 32 + lane];
                acc[j] = fmaf(a.x, v.x, fmaf(a.y, v.y, fmaf(a.z, v.z, fmaf(a.w, v.w, acc[j]))));
            }
        }
        #pragma unroll
        for (int j = 0; j < 2; j++) {
            const float s = wsum(acc[j]);
            if (lane == 0) {
                const int o    = base_o + wid * 2 + j;
                const float tv_ = s + tpb[o];
                t_loc[wid * 2 + j] = tv_;
                u_loc[wid * 2 + j] = zpb[o] - tv_;    // u = zb - t
            }
        }
        __syncthreads();

        // Warp 0: lanes 0..15 each hold one output's contribution; butterfly-16.
        if (wid == 0) {
            float v0x = 0.f, v0y = 0.f, v0z = 0.f, v0w = 0.f;
            float v1x = 0.f, v1y = 0.f, v1z = 0.f, v1w = 0.f;
            if (lane < 16) {
                const int o = base_o + lane;
                const float t_ = t_loc[lane], u_ = u_loc[lane];
                const float a0 = A[o * 3 + 0], a1 = A[o * 3 + 1], a2 = A[o * 3 + 2];
                const float zb_ = zpb[o];
                v0x = 2.f * a0 * u_;  v0y = 2.f * a1 * u_;  v0z = 2.f * a2 * u_;  v0w = u_ * u_;
                v1x = a0 * t_;        v1y = a1 * t_;        v1z = a2 * t_;        v1w = t_ * zb_;
            }
            #pragma unroll
            for (int o2 = 8; o2; o2 >>= 1) {
                v0x += __shfl_xor_sync(0xffffffffu, v0x, o2);
                v0y += __shfl_xor_sync(0xffffffffu, v0y, o2);
                v0z += __shfl_xor_sync(0xffffffffu, v0z, o2);
                v0w += __shfl_xor_sync(0xffffffffu, v0w, o2);
                v1x += __shfl_xor_sync(0xffffffffu, v1x, o2);
                v1y += __shfl_xor_sync(0xffffffffu, v1y, o2);
                v1z += __shfl_xor_sync(0xffffffffu, v1z, o2);
                v1w += __shfl_xor_sync(0xffffffffu, v1w, o2);
            }
            if (lane == 0) {
                g_part[b][qt][0] = make_float4(v0x, v0y, v0z, v0w);
                g_part[b][qt][1] = make_float4(v1x, v1y, v1z, v1w);
            }
        }
    } else {
        // ---------------- globals block (bid == 64) ----------------
        __shared__ float A_sh[HID * 3], W_sh[3 * HID], zpb_sh[HID];

        if (tid < HID * 3) A_sh[tid] = A[tid];
        if (tid < 3 * HID) W_sh[tid] = W[tid];
        if (tid < HID)     zpb_sh[tid] = zpb[tid];
        __syncthreads();

        float* cf = (float*)g_cv;
        const float zl = zpb_sh[lane], zh = zpb_sh[lane + 32];

        if (wid == 0 || wid == 1) {
            // M = A^T A : 6 unique entries, 3 per warp (off-diag pre-doubled)
            const int ii[6] = {0, 1, 2, 0, 0, 1};
            const int jj[6] = {0, 1, 2, 1, 2, 2};
            #pragma unroll
            for (int t = 0; t < 3; t++) {
                const int k = wid * 3 + t;
                float m = wsum(A_sh[lane * 3 + ii[k]] * A_sh[lane * 3 + jj[k]]
                             + A_sh[(lane + 32) * 3 + ii[k]] * A_sh[(lane + 32) * 3 + jj[k]]);
                if (lane == 0) cf[k] = (k < 3) ? m : 2.f * m;
            }
        } else if (wid >= 2 && wid <= 4) {
            // P = W A : row (wid-2), 3 chains
            const int i = wid - 2;
            #pragma unroll
            for (int j = 0; j < 3; j++) {
                float p = wsum(W_sh[i * HID + lane] * A_sh[lane * 3 + j]
                             + W_sh[i * HID + lane + 32] * A_sh[(lane + 32) * 3 + j]);
                if (lane == 0) cf[12 + 4 * i + j] = p;
            }
        } else if (wid == 5) {
            // r = W zb : 3 chains
            #pragma unroll
            for (int i = 0; i < 3; i++) {
                float rr = wsum(W_sh[i * HID + lane] * zl + W_sh[i * HID + lane + 32] * zh);
                if (lane == 0) cf[15 + 4 * i] = rr;
            }
        } else if (wid == 6) {
            if (lane == 0) {
                cf[6] = expf(lg[0]);
                cf[7] = al[0];
                cf[8] = cp[0];
                const float inv = 1.f / (wv[0] + wv[1] + wv[2] + 1e-8f);
                cf[9]  = wv[0] * inv;
                cf[10] = wv[1] * inv;
                cf[11] = wv[2] * inv;
            }
            if (lane >= 1 && lane <= 3) cf[24 + lane - 1] = ob[lane - 1];
        }
    }
}

// ---------------------------------------------------------------------------
// Main: R10's measured-best body (expf x2 + __fdividef sigmoid, 1024 x 256,
// one float4-triple per thread) + uniform partial-summation preamble.
// ---------------------------------------------------------------------------
__global__ void __launch_bounds__(256) fused_main_kernel(
    const float* __restrict__ z, float* __restrict__ out)
{
    const unsigned g  = blockIdx.x * 256u + threadIdx.x;
    const int b  = (int)(g >> 14);        // / HW4
    const int p4 = (int)(g & (HW4 - 1));

    const float4* zb4 = (const float4*)(z   + (size_t)b * ZCH * HWP);
    float4*       ob4 = (float4*)      (out + (size_t)b * ZCH * HWP);

    // front-batched data loads (MLP=3)
    const float4 v0 = zb4[p4];
    const float4 v1 = zb4[p4 + HW4];
    const float4 v2 = zb4[p4 + 2 * HW4];

    // constants (broadcast)
    const float4 c0 = g_cv[0], c1 = g_cv[1], c2 = g_cv[2];
    const float4 c3 = g_cv[3], c4 = g_cv[4], c5 = g_cv[5], c6 = g_cv[6];

    // per-batch: sum the 4 deterministic partials
    const float4 pa0 = g_part[b][0][0], pb0 = g_part[b][1][0],
                 pc0 = g_part[b][2][0], pd0 = g_part[b][3][0];
    const float4 pa1 = g_part[b][0][1], pb1 = g_part[b][1][1],
                 pc1 = g_part[b][2][1], pd1 = g_part[b][3][1];
    const float d0 = (pa0.x + pb0.x) + (pc0.x + pd0.x);
    const float d1 = (pa0.y + pb0.y) + (pc0.y + pd0.y);
    const float d2 = (pa0.z + pb0.z) + (pc0.z + pd0.z);
    const float e  = (pa0.w + pb0.w) + (pc0.w + pd0.w);
    const float q0 = (pa1.x + pb1.x) + (pc1.x + pd1.x);
    const float q1 = (pa1.y + pb1.y) + (pc1.y + pd1.y);
    const float q2 = (pa1.z + pb1.z) + (pc1.z + pd1.z);
    const float s  = (pa1.w + pb1.w) + (pc1.w + pd1.w);

    const float M00 = c0.x, M11 = c0.y, M22 = c0.z, M01 = c0.w;
    const float M02 = c1.x, M12 = c1.y, ngam = -c1.z, alpha = c1.w;
    const float cc = c2.x, w0n = c2.y, w1n = c2.z, w2n = c2.w;

    const float a0[4] = { v0.x, v0.y, v0.z, v0.w };
    const float a1[4] = { v1.x, v1.y, v1.z, v1.w };
    const float a2[4] = { v2.x, v2.y, v2.z, v2.w };
    float o0[4], o1[4], o2[4];

    #pragma unroll
    for (int i = 0; i < 4; i++) {
        const float x = a0[i], y = a1[i], zz = a2[i];

        // dist = z'Mz + d.z + e
        float dist = e;
        dist = fmaf(fmaf(M00, x, fmaf(M01, y, fmaf(M02, zz, d0))), x, dist);
        dist = fmaf(fmaf(M11, y, fmaf(M12, zz, d1)),               y, dist);
        dist = fmaf(fmaf(M22, zz, d2),                             zz, dist);

        // k_lin = q.z + s
        const float klin = fmaf(q0, x, fmaf(q1, y, fmaf(q2, zz, s)));

        const float krbf = __expf(ngam * dist);
        const float t1   = fmaf(alpha, klin, cc);
        const float k    = fmaf(w0n, krbf, fmaf(w1n, klin, w2n * (t1 * t1)));

        // scale = 1 + sigmoid(k) = (2 + E) / (1 + E), E = exp(-k)
        const float E = __expf(-k);
        const float scale = __fdividef(2.f + E, 1.f + E);

        o0[i] = fmaf(scale, fmaf(c3.x, x, fmaf(c3.y, y, fmaf(c3.z, zz, c3.w))), c6.x);
        o1[i] = fmaf(scale, fmaf(c4.x, x, fmaf(c4.y, y, fmaf(c4.z, zz, c4.w))), c6.y);
        o2[i] = fmaf(scale, fmaf(c5.x, x, fmaf(c5.y, y, fmaf(c5.z, zz, c5.w))), c6.z);
    }

    ob4[p4]           = make_float4(o0[0], o0[1], o0[2], o0[3]);
    ob4[p4 + HW4]     = make_float4(o1[0], o1[1], o1[2], o1[3]);
    ob4[p4 + 2 * HW4] = make_float4(o2[0], o2[1], o2[2], o2[3]);
}

// ---------------------------------------------------------------------------
extern "C" void kernel_launch(void* const* d_in, const int* in_sizes, int n_in,
                              void* d_out, int out_size)
{
    const float* z    = (const float*)d_in[0];
    const float* tv   = (const float*)d_in[1];
    const float* zpw  = (const float*)d_in[2];
    const float* zpb  = (const float*)d_in[3];
    const float* tw   = (const float*)d_in[4];
    const float* tpb  = (const float*)d_in[5];
    const float* ow   = (const float*)d_in[6];
    const float* ob   = (const float*)d_in[7];
    const float* lg   = (const float*)d_in[8];
    const float* al   = (const float*)d_in[9];
    const float* cp   = (const float*)d_in[10];
    const float* wv   = (const float*)d_in[11];
    float* out = (float*)d_out;

    const int B = in_sizes[0] / (ZCH * HWP);      // 16

    prep_kernel<<<65, 256>>>(tv, zpw, zpb, tw, tpb, ow, ob, lg, al, cp, wv);
    fused_main_kernel<<<(B * HW4) / 256, 256>>>(z, out);
}